// round 15
// baseline (speedup 1.0000x reference)
#include <cuda_runtime.h>
#include <cstdint>

#define HW_     36864
#define BB      16
#define CC      128
#define NPX     (BB*HW_)
#define NC_     5
#define SCALE_  0.125f
#define THRESH_ 0.7f
#define EPS_    1e-8f

__device__ __forceinline__ float tf32r(float x) {
    uint32_t u;
    asm("cvt.rna.tf32.f32 %0, %1;" : "=r"(u) : "f"(x));
    return __uint_as_float(u);
}
__device__ __forceinline__ void mma_tf32(float* c, float2 a01, float2 a23, float2 b) {
    asm volatile(
        "mma.sync.aligned.m16n8k8.row.col.f32.tf32.tf32.f32 "
        "{%0,%1,%2,%3}, {%4,%5,%6,%7}, {%8,%9}, {%0,%1,%2,%3};"
        : "+f"(c[0]), "+f"(c[1]), "+f"(c[2]), "+f"(c[3])
        : "r"(__float_as_uint(a01.x)), "r"(__float_as_uint(a23.x)),
          "r"(__float_as_uint(a01.y)), "r"(__float_as_uint(a23.y)),
          "r"(__float_as_uint(b.x)),   "r"(__float_as_uint(b.y)));
}
#define FMA2(d, a, b) asm("fma.rn.f32x2 %0, %1, %2, %0;" : "+l"(d) : "l"(a), "l"(b))
#define PACK2(d, s)   asm("mov.b64 %0, {%1, %1};" : "=l"(d) : "r"(s))
#define UNPK2(lo, hi, s) asm("mov.b64 {%0, %1}, %2;" : "=r"(lo), "=r"(hi) : "l"(s))
__device__ __forceinline__ int gpos(int k) {
    return (k & ~7) + 2*(k & 3) + ((k >> 2) & 1);
}

// ---- scratch ----
__device__ float g_down[NPX*16];
__device__ float g_mid [NPX*8];
__device__ float g_BA  [64];
__device__ float g_B1s [8*16];
__device__ float g_McI [24*128];
__device__ float g_Wc1I[128*160];
__device__ float g_W2I [128*128];
__device__ float g_num [BB*NC_*CC];
__device__ float g_xn2 [BB*CC];
__device__ float g_cn2 [NC_*CC];
__device__ unsigned int g_ctr;

// ---------------------------------------------------------------------------
__global__ void k_init(const float* __restrict__ B1, const float* __restrict__ A2,
                       const float* __restrict__ A1)
{
    int t = threadIdx.x;
    for (int i = t; i < BB*NC_*CC; i += 256) g_num[i] = 0.f;
    for (int i = t; i < BB*CC;     i += 256) g_xn2[i] = 0.f;
    for (int i = t; i < NC_*CC;    i += 256) g_cn2[i] = 0.f;
    if (t == 0) g_ctr = 0u;
    if (t < 128) g_B1s[t] = B1[t] * SCALE_;
    if (t < 64) {
        int r = t >> 3, q = t & 7;
        float s = 0.f;
        #pragma unroll
        for (int j = 0; j < 16; j++) s += B1[r*16 + j] * A2[j*8 + q];
        g_BA[r*8 + q] = s * SCALE_;
    }
    __syncthreads();
    for (int i = t; i < 24*128; i += 256) {
        int n = i >> 7, k = i & 127;
        float s = 0.f;
        #pragma unroll
        for (int r = 0; r < 8; r++) {
            float m = (n < 16) ? g_B1s[r*16 + n] : g_BA[r*8 + (n - 16)];
            s += A1[k*8 + r] * m;
        }
        g_McI[n*128 + gpos(k)] = tf32r(s);
    }
}

// ---------------------------------------------------------------------------
__global__ void k_init2(const float* __restrict__ W1, const float* __restrict__ W2,
                        const float* __restrict__ B2, const float* __restrict__ cwp)
{
    float cw   = 1.f / (1.f + __expf(-cwp[0]));
    float omcw = 1.f - cw;
    float cws  = cw * SCALE_;
    int step = blockDim.x * gridDim.x;
    int t0   = blockIdx.x * blockDim.x + threadIdx.x;
    for (int i = t0; i < 152*128; i += step) {
        int k = i >> 7, n = i & 127;
        float v;
        if (k < 128) v = omcw * W1[k*CC + n];
        else if (k < 136) {
            int r = k - 128;
            float s = 0.f;
            for (int j = 0; j < 128; j++) s += B2[r*CC + j] * W1[j*CC + n];
            v = cws * s;
        } else v = W1[(k - 8)*CC + n];
        g_Wc1I[n*160 + gpos(k)] = tf32r(v);
    }
    for (int i = t0; i < 128*128; i += step) {
        int k = i >> 7, n = i & 127;
        g_W2I[n*128 + gpos(k)] = tf32r(W2[k*CC + n]);
    }
}

// ---------------------------------------------------------------------------
// K1: smem-staged tf32 HMMA (R12 proven version)
// ---------------------------------------------------------------------------
#define ST0 132
#define L_SMEM (128*ST0)

__global__ void __launch_bounds__(256, 3)
k_lora(const float* __restrict__ x)
{
    extern __shared__ float sl[];
    int tid  = threadIdx.x;
    int wid  = tid >> 5;
    int lane = tid & 31;
    int gid  = lane >> 2;
    int tig  = lane & 3;
    size_t px0 = (size_t)blockIdx.x * 128;

    #pragma unroll 4
    for (int pass = 0; pass < 16; pass++) {
        int i  = pass*256 + tid;
        int px = i >> 5, c4 = (i & 31) * 4;
        float4 v = *(const float4*)(x + (px0 + px)*CC + c4);
        float4 o;
        o.x = tf32r(v.x); o.y = tf32r(v.y); o.z = tf32r(v.z); o.w = tf32r(v.w);
        *(float4*)(sl + px*ST0 + c4) = o;
    }
    __syncthreads();

    float acc[3][4];
    #pragma unroll
    for (int nt = 0; nt < 3; nt++)
        #pragma unroll
        for (int v = 0; v < 4; v++) acc[nt][v] = 0.f;

    const float* Ar0 = sl + (wid*16 + gid)*ST0;
    const float* Ar1 = Ar0 + 8*ST0;
    #pragma unroll
    for (int ks = 0; ks < 16; ks++) {
        int k0 = ks*8 + tig;
        float2 a01 = make_float2(Ar0[k0], Ar0[k0+4]);
        float2 a23 = make_float2(Ar1[k0], Ar1[k0+4]);
        #pragma unroll
        for (int nt = 0; nt < 3; nt++) {
            float2 b = __ldg((const float2*)(g_McI + (nt*8 + gid)*128 + ks*8 + 2*tig));
            mma_tf32(acc[nt], a01, a23, b);
        }
    }

    #pragma unroll
    for (int nt = 0; nt < 3; nt++)
        #pragma unroll
        for (int h2 = 0; h2 < 2; h2++) {
            size_t px = px0 + wid*16 + gid + h2*8;
            float2 o = make_float2(acc[nt][2*h2], acc[nt][2*h2+1]);
            if (nt < 2) *(float2*)(g_down + px*16 + nt*8 + 2*tig) = o;
            else        *(float2*)(g_mid  + px*8  + 2*tig)        = o;
        }
}

// ---------------------------------------------------------------------------
// K_num: 4 batches (2 f32x2 pairs) per block, 2304 blocks (R14 proven)
// ---------------------------------------------------------------------------
#define K2CHUNK 64
__global__ void k_num(const float* __restrict__ cf, const float* __restrict__ B2)
{
    __shared__ float2 midp[2][K2CHUNK][8];
    int c   = threadIdx.x;
    int hw0 = blockIdx.x * K2CHUNK;
    int b0  = blockIdx.y * 4;
    bool do_cn = (blockIdx.y == 0);

    unsigned long long b2cc[8];
    #pragma unroll
    for (int r = 0; r < 8; r++) {
        uint32_t u = __float_as_uint(B2[r*CC + c] * SCALE_);
        PACK2(b2cc[r], u);
    }

    const float4* midg = (const float4*)g_mid;
    for (int i = threadIdx.x; i < 4*K2CHUNK*2; i += 128) {
        int bb = i / (K2CHUNK*2), rem = i % (K2CHUNK*2);
        int h = rem >> 1, part = rem & 1;
        float4 v = midg[((size_t)(b0+bb)*HW_ + hw0 + h)*2 + part];
        int p = bb >> 1, s = bb & 1;
        float* dst = (float*)&midp[p][h][part*4];
        dst[0*2 + s] = v.x; dst[1*2 + s] = v.y;
        dst[2*2 + s] = v.z; dst[3*2 + s] = v.w;
    }
    __syncthreads();

    unsigned long long accn2[2][5], accx2[2];
    float accc[5];
    #pragma unroll
    for (int p = 0; p < 2; p++) {
        accx2[p] = 0ull;
        #pragma unroll
        for (int n = 0; n < 5; n++) accn2[p][n] = 0ull;
    }
    #pragma unroll
    for (int n = 0; n < 5; n++) accc[n] = 0.f;

    #pragma unroll 2
    for (int h = 0; h < K2CHUNK; h++) {
        unsigned long long xl2[2];
        #pragma unroll
        for (int p = 0; p < 2; p++) {
            unsigned long long a = 0ull;
            const unsigned long long* mp = (const unsigned long long*)&midp[p][h][0];
            #pragma unroll
            for (int q = 0; q < 8; q++) FMA2(a, mp[q], b2cc[q]);
            xl2[p] = a;
            FMA2(accx2[p], a, a);
        }
        #pragma unroll
        for (int n = 0; n < 5; n++) {
            float cv = cf[((size_t)n*HW_ + hw0 + h)*CC + c];
            accc[n] += cv*cv;
            unsigned long long cvv;
            PACK2(cvv, __float_as_uint(cv));
            FMA2(accn2[0][n], xl2[0], cvv);
            FMA2(accn2[1][n], xl2[1], cvv);
        }
    }
    #pragma unroll
    for (int p = 0; p < 2; p++) {
        uint32_t lo, hi;
        #pragma unroll
        for (int n = 0; n < 5; n++) {
            UNPK2(lo, hi, accn2[p][n]);
            atomicAdd(&g_num[((b0+2*p  )*NC_ + n)*CC + c], __uint_as_float(lo));
            atomicAdd(&g_num[((b0+2*p+1)*NC_ + n)*CC + c], __uint_as_float(hi));
        }
        UNPK2(lo, hi, accx2[p]);
        atomicAdd(&g_xn2[(b0+2*p  )*CC + c], __uint_as_float(lo));
        atomicAdd(&g_xn2[(b0+2*p+1)*CC + c], __uint_as_float(hi));
    }
    if (do_cn) {
        #pragma unroll
        for (int n = 0; n < 5; n++) atomicAdd(&g_cn2[n*CC + c], accc[n]);
    }
}

// ---------------------------------------------------------------------------
// K_fuse: persistent, 256 threads, 3 blocks/SM. MLP tile = 96 px (6 m-tiles
// per warp). Weights via __ldg from L1-resident globals.
// ---------------------------------------------------------------------------
#define TPX     96
#define MT_     6
#define UPX     256
#define ST1     156
#define ST2     132
#define SMEM_FL (TPX*ST1)
#define NBLK    444

__global__ void __launch_bounds__(256, 3)
k_fuse(const float* __restrict__ cf,
       const float* __restrict__ b1, const float* __restrict__ b2,
       const float* __restrict__ B2,
       float* __restrict__ out)
{
    extern __shared__ float sm[];
    __shared__ int   sIdx;
    __shared__ float s_part[BB][NC_][2];
    __shared__ float s_bs[BB];
    __shared__ int   s_bi[BB];
    __shared__ int   s_ml[BB], s_ul[BB];
    __shared__ int   s_mc;
    int tid  = threadIdx.x;
    int wid  = tid >> 5;
    int lane = tid & 31;
    int gid  = lane >> 2;
    int tig  = lane & 3;
    int nbase = wid * 16;

    // ---- sims prologue ----
    if (tid < BB*NC_*2) {
        int b = tid / (NC_*2), r = tid % (NC_*2), n = r >> 1, hf = r & 1;
        float s = 0.f;
        #pragma unroll 4
        for (int j = 0; j < 64; j++) {
            int c = hf*64 + j;
            float xn = sqrtf(g_xn2[b*CC + c]);
            float cn = sqrtf(g_cn2[n*CC + c]);
            s += g_num[(b*NC_ + n)*CC + c] / (fmaxf(xn, EPS_) * fmaxf(cn, EPS_));
        }
        s_part[b][n][hf] = s;
    }
    __syncthreads();
    if (tid < BB) {
        float best = -1e30f; int bi = 0;
        #pragma unroll
        for (int n = 0; n < NC_; n++) {
            float v = (s_part[tid][n][0] + s_part[tid][n][1]) * (1.0f/CC);
            if (v > best) { best = v; bi = n; }
        }
        s_bs[tid] = best; s_bi[tid] = bi;
    }
    __syncthreads();
    if (tid == 0) {
        int m = 0, u = 0;
        #pragma unroll
        for (int b = 0; b < BB; b++) {
            if (s_bs[b] > THRESH_) s_ml[m++] = b;
            else                   s_ul[u++] = b;
        }
        s_mc = m;
    }
    __syncthreads();
    int mc     = s_mc;
    int totalM = mc * (HW_/TPX);
    int total  = totalM + (BB - mc) * (HW_/UPX);

    while (true) {
        if (tid == 0) sIdx = (int)atomicAdd(&g_ctr, 1u);
        __syncthreads();
        int idx = sIdx;
        if (idx >= total) break;

        if (idx >= totalM) {
            // ===== x_lora item (unmasked batch, 256 px, thread-per-px) ======
            int j  = idx - totalM;
            int b  = s_ul[j / (HW_/UPX)];
            size_t px = (size_t)b*HW_ + (size_t)(j % (HW_/UPX))*UPX + tid;

            float4 m0 = *(const float4*)(g_mid + px*8);
            float4 m1 = *(const float4*)(g_mid + px*8 + 4);
            m0.x *= SCALE_; m0.y *= SCALE_; m0.z *= SCALE_; m0.w *= SCALE_;
            m1.x *= SCALE_; m1.y *= SCALE_; m1.z *= SCALE_; m1.w *= SCALE_;

            float4* og = (float4*)(out + px*CC);
            #pragma unroll 4
            for (int c4 = 0; c4 < 32; c4++) {
                float4 r = make_float4(0.f,0.f,0.f,0.f);
                const float* bq = B2 + c4*4;
                #pragma unroll
                for (int q = 0; q < 8; q++) {
                    float mv = (q < 4) ? ((q==0)?m0.x:(q==1)?m0.y:(q==2)?m0.z:m0.w)
                                       : ((q==4)?m1.x:(q==5)?m1.y:(q==6)?m1.z:m1.w);
                    float4 bv = __ldg((const float4*)(bq + q*CC));
                    r.x += mv*bv.x; r.y += mv*bv.y; r.z += mv*bv.z; r.w += mv*bv.w;
                }
                og[c4] = r;
            }
            continue;
        }

        // ================= MLP item (masked batch, 96 px) ==================
        int b   = s_ml[idx / (HW_/TPX)];
        int hw0 = (idx % (HW_/TPX)) * TPX;
        int bi  = s_bi[b];

        // ---- build A tile (interleaved, tf32): 96px x 128c ----
        const float4* bp = (const float4*)(cf + ((size_t)bi*HW_ + hw0)*CC);
        #pragma unroll 4
        for (int pass = 0; pass < 12; pass++) {
            int i  = pass*256 + tid;
            int px = i >> 5, c4 = (i & 31) * 4;
            float4 v = bp[i];
            float* dst = sm + px*ST1 + (c4 & ~7) + ((c4 >> 2) & 1);
            dst[0] = tf32r(v.x); dst[2] = tf32r(v.y);
            dst[4] = tf32r(v.z); dst[6] = tf32r(v.w);
        }
        if (tid < 192) {   // mid -> cols 128..135 (96px x 2 halves)
            int px = tid >> 1, hf = tid & 1;
            float4 v = *(const float4*)(g_mid + ((size_t)b*HW_ + hw0 + px)*8 + hf*4);
            float* dst = sm + px*ST1 + 128 + hf;
            dst[0] = tf32r(v.x); dst[2] = tf32r(v.y);
            dst[4] = tf32r(v.z); dst[6] = tf32r(v.w);
        }
        for (int i = tid; i < 384; i += 256) {  // down -> cols 136..151
            int px = i >> 2, q = i & 3;
            float4 v = *(const float4*)(g_down + ((size_t)b*HW_ + hw0 + px)*16 + q*4);
            float* dst = sm + px*ST1 + 136 + (q >> 1)*8 + (q & 1);
            dst[0] = tf32r(v.x); dst[2] = tf32r(v.y);
            dst[4] = tf32r(v.z); dst[6] = tf32r(v.w);
        }
        __syncthreads();

        // ---- GEMM1: 19 k-steps over K=152 ----
        float acc[MT_][2][4];
        #pragma unroll
        for (int mt = 0; mt < MT_; mt++)
            #pragma unroll
            for (int nt = 0; nt < 2; nt++)
                #pragma unroll
                for (int v = 0; v < 4; v++) acc[mt][nt][v] = 0.f;

        #pragma unroll 1
        for (int ks = 0; ks < 19; ks++) {
            int kb = ks*8 + 2*tig;
            float2 bf0 = __ldg((const float2*)(g_Wc1I + (nbase + gid)*160 + kb));
            float2 bf1 = __ldg((const float2*)(g_Wc1I + (nbase + 8 + gid)*160 + kb));
            #pragma unroll
            for (int mt = 0; mt < MT_; mt++) {
                float2 a01 = *(const float2*)(sm + (mt*16 + gid)*ST1 + kb);
                float2 a23 = *(const float2*)(sm + (mt*16 + 8 + gid)*ST1 + kb);
                mma_tf32(acc[mt][0], a01, a23, bf0);
                mma_tf32(acc[mt][1], a01, a23, bf1);
            }
        }
        __syncthreads();

        // ---- epilogue1: silu(h+b1) -> act2 ----
        #pragma unroll
        for (int mt = 0; mt < MT_; mt++)
            #pragma unroll
            for (int nt = 0; nt < 2; nt++)
                #pragma unroll
                for (int v = 0; v < 4; v++) {
                    int row = mt*16 + gid + ((v >> 1) << 3);
                    int col = nbase + nt*8 + 2*tig + (v & 1);
                    float h = acc[mt][nt][v] + __ldg(b1 + col);
                    float s = h / (1.f + __expf(-h));
                    sm[row*ST2 + gpos(col)] = tf32r(s);
                }
        __syncthreads();

        // ---- GEMM2: 16 k-steps over K=128 ----
        #pragma unroll
        for (int mt = 0; mt < MT_; mt++)
            #pragma unroll
            for (int nt = 0; nt < 2; nt++)
                #pragma unroll
                for (int v = 0; v < 4; v++) acc[mt][nt][v] = 0.f;

        #pragma unroll 1
        for (int ks = 0; ks < 16; ks++) {
            int kb = ks*8 + 2*tig;
            float2 bf0 = __ldg((const float2*)(g_W2I + (nbase + gid)*128 + kb));
            float2 bf1 = __ldg((const float2*)(g_W2I + (nbase + 8 + gid)*128 + kb));
            #pragma unroll
            for (int mt = 0; mt < MT_; mt++) {
                float2 a01 = *(const float2*)(sm + (mt*16 + gid)*ST2 + kb);
                float2 a23 = *(const float2*)(sm + (mt*16 + 8 + gid)*ST2 + kb);
                mma_tf32(acc[mt][0], a01, a23, bf0);
                mma_tf32(acc[mt][1], a01, a23, bf1);
            }
        }

        // ---- epilogue2: out = D + b2 ----
        #pragma unroll
        for (int mt = 0; mt < MT_; mt++)
            #pragma unroll
            for (int nt = 0; nt < 2; nt++)
                #pragma unroll
                for (int h2 = 0; h2 < 2; h2++) {
                    int row = mt*16 + gid + h2*8;
                    int col = nbase + nt*8 + 2*tig;
                    float2 o;
                    o.x = acc[mt][nt][h2*2 + 0] + __ldg(b2 + col);
                    o.y = acc[mt][nt][h2*2 + 1] + __ldg(b2 + col + 1);
                    *(float2*)(out + ((size_t)b*HW_ + hw0 + row)*CC + col) = o;
                }
        __syncthreads();
    }
}

// ---------------------------------------------------------------------------
extern "C" void kernel_launch(void* const* d_in, const int* in_sizes, int n_in,
                              void* d_out, int out_size)
{
    const float* x   = (const float*)d_in[0];
    const float* A1  = (const float*)d_in[1];
    const float* B1  = (const float*)d_in[2];
    const float* A2  = (const float*)d_in[3];
    const float* B2  = (const float*)d_in[4];
    const float* W1  = (const float*)d_in[5];
    const float* b1v = (const float*)d_in[6];
    const float* W2  = (const float*)d_in[7];
    const float* b2v = (const float*)d_in[8];
    const float* cw  = (const float*)d_in[9];
    const float* cf  = (const float*)d_in[10];
    float* out = (float*)d_out;

    cudaFuncSetAttribute(k_fuse, cudaFuncAttributeMaxDynamicSharedMemorySize,
                         SMEM_FL * (int)sizeof(float));
    cudaFuncSetAttribute(k_lora, cudaFuncAttributeMaxDynamicSharedMemorySize,
                         L_SMEM * (int)sizeof(float));

    k_init  <<<1, 256>>>(B1, A2, A1);
    k_init2 <<<8, 256>>>(W1, W2, B2, cw);
    k_lora  <<<NPX/128, 256, L_SMEM * (int)sizeof(float)>>>(x);
    k_num   <<<dim3(HW_/K2CHUNK, 4), 128>>>(cf, B2);
    k_fuse  <<<NBLK, 256, SMEM_FL * (int)sizeof(float)>>>(
                cf, b1v, b2v, B2, out);
}

// round 16
// speedup vs baseline: 1.1704x; 1.1704x over previous
#include <cuda_runtime.h>
#include <cstdint>

#define HW_     36864
#define BB      16
#define CC      128
#define NPX     (BB*HW_)
#define NC_     5
#define SCALE_  0.125f
#define THRESH_ 0.7f
#define EPS_    1e-8f

__device__ __forceinline__ float tf32r(float x) {
    uint32_t u;
    asm("cvt.rna.tf32.f32 %0, %1;" : "=r"(u) : "f"(x));
    return __uint_as_float(u);
}
__device__ __forceinline__ void mma_tf32(float* c, float2 a01, float2 a23, float2 b) {
    asm volatile(
        "mma.sync.aligned.m16n8k8.row.col.f32.tf32.tf32.f32 "
        "{%0,%1,%2,%3}, {%4,%5,%6,%7}, {%8,%9}, {%0,%1,%2,%3};"
        : "+f"(c[0]), "+f"(c[1]), "+f"(c[2]), "+f"(c[3])
        : "r"(__float_as_uint(a01.x)), "r"(__float_as_uint(a23.x)),
          "r"(__float_as_uint(a01.y)), "r"(__float_as_uint(a23.y)),
          "r"(__float_as_uint(b.x)),   "r"(__float_as_uint(b.y)));
}
#define FMA2(d, a, b) asm("fma.rn.f32x2 %0, %1, %2, %0;" : "+l"(d) : "l"(a), "l"(b))
#define PACK2(d, s)   asm("mov.b64 %0, {%1, %1};" : "=l"(d) : "r"(s))
#define UNPK2(lo, hi, s) asm("mov.b64 {%0, %1}, %2;" : "=r"(lo), "=r"(hi) : "l"(s))
__device__ __forceinline__ int gpos(int k) {
    return (k & ~7) + 2*(k & 3) + ((k >> 2) & 1);
}

// ---- scratch ----
__device__ float g_down[NPX*16];
__device__ float g_mid [NPX*8];
__device__ float g_BA  [64];
__device__ float g_B1s [8*16];
__device__ float g_McI [24*128];
__device__ float g_Wc1I[128*160];
__device__ float g_W2I [128*128];
__device__ float g_num [BB*NC_*CC];
__device__ float g_xn2 [BB*CC];
__device__ float g_cn2 [NC_*CC];
__device__ unsigned int g_ctr;

// ---------------------------------------------------------------------------
__global__ void k_init(const float* __restrict__ B1, const float* __restrict__ A2,
                       const float* __restrict__ A1)
{
    int t = threadIdx.x;
    for (int i = t; i < BB*NC_*CC; i += 256) g_num[i] = 0.f;
    for (int i = t; i < BB*CC;     i += 256) g_xn2[i] = 0.f;
    for (int i = t; i < NC_*CC;    i += 256) g_cn2[i] = 0.f;
    if (t == 0) g_ctr = 0u;
    if (t < 128) g_B1s[t] = B1[t] * SCALE_;
    if (t < 64) {
        int r = t >> 3, q = t & 7;
        float s = 0.f;
        #pragma unroll
        for (int j = 0; j < 16; j++) s += B1[r*16 + j] * A2[j*8 + q];
        g_BA[r*8 + q] = s * SCALE_;
    }
    __syncthreads();
    for (int i = t; i < 24*128; i += 256) {
        int n = i >> 7, k = i & 127;
        float s = 0.f;
        #pragma unroll
        for (int r = 0; r < 8; r++) {
            float m = (n < 16) ? g_B1s[r*16 + n] : g_BA[r*8 + (n - 16)];
            s += A1[k*8 + r] * m;
        }
        g_McI[n*128 + gpos(k)] = tf32r(s);
    }
}

// ---------------------------------------------------------------------------
__global__ void k_init2(const float* __restrict__ W1, const float* __restrict__ W2,
                        const float* __restrict__ B2, const float* __restrict__ cwp)
{
    float cw   = 1.f / (1.f + __expf(-cwp[0]));
    float omcw = 1.f - cw;
    float cws  = cw * SCALE_;
    int step = blockDim.x * gridDim.x;
    int t0   = blockIdx.x * blockDim.x + threadIdx.x;
    for (int i = t0; i < 152*128; i += step) {
        int k = i >> 7, n = i & 127;
        float v;
        if (k < 128) v = omcw * W1[k*CC + n];
        else if (k < 136) {
            int r = k - 128;
            float s = 0.f;
            for (int j = 0; j < 128; j++) s += B2[r*CC + j] * W1[j*CC + n];
            v = cws * s;
        } else v = W1[(k - 8)*CC + n];
        g_Wc1I[n*160 + gpos(k)] = tf32r(v);
    }
    for (int i = t0; i < 128*128; i += step) {
        int k = i >> 7, n = i & 127;
        g_W2I[n*128 + gpos(k)] = tf32r(W2[k*CC + n]);
    }
}

// ---------------------------------------------------------------------------
// K1: smem-staged tf32 HMMA (R12 proven version)
// ---------------------------------------------------------------------------
#define ST0 132
#define L_SMEM (128*ST0)

__global__ void __launch_bounds__(256, 3)
k_lora(const float* __restrict__ x)
{
    extern __shared__ float sl[];
    int tid  = threadIdx.x;
    int wid  = tid >> 5;
    int lane = tid & 31;
    int gid  = lane >> 2;
    int tig  = lane & 3;
    size_t px0 = (size_t)blockIdx.x * 128;

    #pragma unroll 4
    for (int pass = 0; pass < 16; pass++) {
        int i  = pass*256 + tid;
        int px = i >> 5, c4 = (i & 31) * 4;
        float4 v = *(const float4*)(x + (px0 + px)*CC + c4);
        float4 o;
        o.x = tf32r(v.x); o.y = tf32r(v.y); o.z = tf32r(v.z); o.w = tf32r(v.w);
        *(float4*)(sl + px*ST0 + c4) = o;
    }
    __syncthreads();

    float acc[3][4];
    #pragma unroll
    for (int nt = 0; nt < 3; nt++)
        #pragma unroll
        for (int v = 0; v < 4; v++) acc[nt][v] = 0.f;

    const float* Ar0 = sl + (wid*16 + gid)*ST0;
    const float* Ar1 = Ar0 + 8*ST0;
    #pragma unroll
    for (int ks = 0; ks < 16; ks++) {
        int k0 = ks*8 + tig;
        float2 a01 = make_float2(Ar0[k0], Ar0[k0+4]);
        float2 a23 = make_float2(Ar1[k0], Ar1[k0+4]);
        #pragma unroll
        for (int nt = 0; nt < 3; nt++) {
            float2 b = __ldg((const float2*)(g_McI + (nt*8 + gid)*128 + ks*8 + 2*tig));
            mma_tf32(acc[nt], a01, a23, b);
        }
    }

    #pragma unroll
    for (int nt = 0; nt < 3; nt++)
        #pragma unroll
        for (int h2 = 0; h2 < 2; h2++) {
            size_t px = px0 + wid*16 + gid + h2*8;
            float2 o = make_float2(acc[nt][2*h2], acc[nt][2*h2+1]);
            if (nt < 2) *(float2*)(g_down + px*16 + nt*8 + 2*tig) = o;
            else        *(float2*)(g_mid  + px*8  + 2*tig)        = o;
        }
}

// ---------------------------------------------------------------------------
// K_num: 4 batches (2 f32x2 pairs) per block, 2304 blocks (R14 proven)
// ---------------------------------------------------------------------------
#define K2CHUNK 64
__global__ void k_num(const float* __restrict__ cf, const float* __restrict__ B2)
{
    __shared__ float2 midp[2][K2CHUNK][8];
    int c   = threadIdx.x;
    int hw0 = blockIdx.x * K2CHUNK;
    int b0  = blockIdx.y * 4;
    bool do_cn = (blockIdx.y == 0);

    unsigned long long b2cc[8];
    #pragma unroll
    for (int r = 0; r < 8; r++) {
        uint32_t u = __float_as_uint(B2[r*CC + c] * SCALE_);
        PACK2(b2cc[r], u);
    }

    const float4* midg = (const float4*)g_mid;
    for (int i = threadIdx.x; i < 4*K2CHUNK*2; i += 128) {
        int bb = i / (K2CHUNK*2), rem = i % (K2CHUNK*2);
        int h = rem >> 1, part = rem & 1;
        float4 v = midg[((size_t)(b0+bb)*HW_ + hw0 + h)*2 + part];
        int p = bb >> 1, s = bb & 1;
        float* dst = (float*)&midp[p][h][part*4];
        dst[0*2 + s] = v.x; dst[1*2 + s] = v.y;
        dst[2*2 + s] = v.z; dst[3*2 + s] = v.w;
    }
    __syncthreads();

    unsigned long long accn2[2][5], accx2[2];
    float accc[5];
    #pragma unroll
    for (int p = 0; p < 2; p++) {
        accx2[p] = 0ull;
        #pragma unroll
        for (int n = 0; n < 5; n++) accn2[p][n] = 0ull;
    }
    #pragma unroll
    for (int n = 0; n < 5; n++) accc[n] = 0.f;

    #pragma unroll 2
    for (int h = 0; h < K2CHUNK; h++) {
        unsigned long long xl2[2];
        #pragma unroll
        for (int p = 0; p < 2; p++) {
            unsigned long long a = 0ull;
            const unsigned long long* mp = (const unsigned long long*)&midp[p][h][0];
            #pragma unroll
            for (int q = 0; q < 8; q++) FMA2(a, mp[q], b2cc[q]);
            xl2[p] = a;
            FMA2(accx2[p], a, a);
        }
        #pragma unroll
        for (int n = 0; n < 5; n++) {
            float cv = cf[((size_t)n*HW_ + hw0 + h)*CC + c];
            accc[n] += cv*cv;
            unsigned long long cvv;
            PACK2(cvv, __float_as_uint(cv));
            FMA2(accn2[0][n], xl2[0], cvv);
            FMA2(accn2[1][n], xl2[1], cvv);
        }
    }
    #pragma unroll
    for (int p = 0; p < 2; p++) {
        uint32_t lo, hi;
        #pragma unroll
        for (int n = 0; n < 5; n++) {
            UNPK2(lo, hi, accn2[p][n]);
            atomicAdd(&g_num[((b0+2*p  )*NC_ + n)*CC + c], __uint_as_float(lo));
            atomicAdd(&g_num[((b0+2*p+1)*NC_ + n)*CC + c], __uint_as_float(hi));
        }
        UNPK2(lo, hi, accx2[p]);
        atomicAdd(&g_xn2[(b0+2*p  )*CC + c], __uint_as_float(lo));
        atomicAdd(&g_xn2[(b0+2*p+1)*CC + c], __uint_as_float(hi));
    }
    if (do_cn) {
        #pragma unroll
        for (int n = 0; n < 5; n++) atomicAdd(&g_cn2[n*CC + c], accc[n]);
    }
}

// ---------------------------------------------------------------------------
// K_fuse: persistent, 256 threads, 2 blocks/SM (R14 config). xlora branch
// rewritten warp-cooperative for coalesced 512B stores.
// ---------------------------------------------------------------------------
#define TPX     128
#define UPX     256
#define ST1     156
#define ST2     132
#define SMEM_FL (128*ST1)
#define NBLK    296

__global__ void __launch_bounds__(256, 2)
k_fuse(const float* __restrict__ cf,
       const float* __restrict__ b1, const float* __restrict__ b2,
       const float* __restrict__ B2,
       float* __restrict__ out)
{
    extern __shared__ float sm[];
    __shared__ int   sIdx;
    __shared__ float s_part[BB][NC_][2];
    __shared__ float s_bs[BB];
    __shared__ int   s_bi[BB];
    __shared__ int   s_ml[BB], s_ul[BB];
    __shared__ int   s_mc;
    int tid  = threadIdx.x;
    int wid  = tid >> 5;
    int lane = tid & 31;
    int gid  = lane >> 2;
    int tig  = lane & 3;
    int nbase = wid * 16;

    // ---- sims prologue ----
    if (tid < BB*NC_*2) {
        int b = tid / (NC_*2), r = tid % (NC_*2), n = r >> 1, hf = r & 1;
        float s = 0.f;
        #pragma unroll 4
        for (int j = 0; j < 64; j++) {
            int c = hf*64 + j;
            float xn = sqrtf(g_xn2[b*CC + c]);
            float cn = sqrtf(g_cn2[n*CC + c]);
            s += g_num[(b*NC_ + n)*CC + c] / (fmaxf(xn, EPS_) * fmaxf(cn, EPS_));
        }
        s_part[b][n][hf] = s;
    }
    __syncthreads();
    if (tid < BB) {
        float best = -1e30f; int bi = 0;
        #pragma unroll
        for (int n = 0; n < NC_; n++) {
            float v = (s_part[tid][n][0] + s_part[tid][n][1]) * (1.0f/CC);
            if (v > best) { best = v; bi = n; }
        }
        s_bs[tid] = best; s_bi[tid] = bi;
    }
    __syncthreads();
    if (tid == 0) {
        int m = 0, u = 0;
        #pragma unroll
        for (int b = 0; b < BB; b++) {
            if (s_bs[b] > THRESH_) s_ml[m++] = b;
            else                   s_ul[u++] = b;
        }
        s_mc = m;
    }
    __syncthreads();
    int mc     = s_mc;
    int totalM = mc * (HW_/TPX);
    int total  = totalM + (BB - mc) * (HW_/UPX);

    // B2 columns for this lane (x SCALE), used by the xlora branch
    float4 bv4[8];
    #pragma unroll
    for (int q = 0; q < 8; q++) {
        float4 v = __ldg((const float4*)(B2 + q*CC + lane*4));
        v.x *= SCALE_; v.y *= SCALE_; v.z *= SCALE_; v.w *= SCALE_;
        bv4[q] = v;
    }

    while (true) {
        if (tid == 0) sIdx = (int)atomicAdd(&g_ctr, 1u);
        __syncthreads();
        int idx = sIdx;
        if (idx >= total) break;

        if (idx >= totalM) {
            // ===== x_lora item (unmasked batch, 256 px, warp-cooperative) ===
            int j  = idx - totalM;
            int b  = s_ul[j / (HW_/UPX)];
            size_t pxb = (size_t)b*HW_ + (size_t)(j % (HW_/UPX))*UPX + wid*32;

            // lane owns pixel (pxb+lane)'s mid
            float4 m0 = *(const float4*)(g_mid + (pxb + lane)*8);
            float4 m1 = *(const float4*)(g_mid + (pxb + lane)*8 + 4);
            float mreg[8] = {m0.x, m0.y, m0.z, m0.w, m1.x, m1.y, m1.z, m1.w};

            #pragma unroll 4
            for (int p = 0; p < 32; p++) {
                float mm[8];
                #pragma unroll
                for (int q = 0; q < 8; q++)
                    mm[q] = __shfl_sync(0xffffffffu, mreg[q], p);
                float4 r = make_float4(0.f, 0.f, 0.f, 0.f);
                #pragma unroll
                for (int q = 0; q < 8; q++) {
                    r.x += mm[q]*bv4[q].x; r.y += mm[q]*bv4[q].y;
                    r.z += mm[q]*bv4[q].z; r.w += mm[q]*bv4[q].w;
                }
                *(float4*)(out + (pxb + p)*CC + lane*4) = r;   // coalesced 512B
            }
            continue;
        }

        // ================= MLP item (masked batch, 128 px) ==================
        int b   = s_ml[idx / (HW_/TPX)];
        int hw0 = (idx % (HW_/TPX)) * TPX;
        int bi  = s_bi[b];

        const float4* bp = (const float4*)(cf + ((size_t)bi*HW_ + hw0)*CC);
        #pragma unroll 4
        for (int pass = 0; pass < 16; pass++) {
            int i  = pass*256 + tid;
            int px = i >> 5, c4 = (i & 31) * 4;
            float4 v = bp[i];
            float* dst = sm + px*ST1 + (c4 & ~7) + ((c4 >> 2) & 1);
            dst[0] = tf32r(v.x); dst[2] = tf32r(v.y);
            dst[4] = tf32r(v.z); dst[6] = tf32r(v.w);
        }
        {
            int px = tid >> 1, hf = tid & 1;
            float4 v = *(const float4*)(g_mid + ((size_t)b*HW_ + hw0 + px)*8 + hf*4);
            float* dst = sm + px*ST1 + 128 + hf;
            dst[0] = tf32r(v.x); dst[2] = tf32r(v.y);
            dst[4] = tf32r(v.z); dst[6] = tf32r(v.w);
        }
        #pragma unroll
        for (int j = 0; j < 2; j++) {
            int i  = j*256 + tid;
            int px = i >> 2, q = i & 3;
            float4 v = *(const float4*)(g_down + ((size_t)b*HW_ + hw0 + px)*16 + q*4);
            float* dst = sm + px*ST1 + 136 + (q >> 1)*8 + (q & 1);
            dst[0] = tf32r(v.x); dst[2] = tf32r(v.y);
            dst[4] = tf32r(v.z); dst[6] = tf32r(v.w);
        }
        __syncthreads();

        float acc[8][2][4];
        #pragma unroll
        for (int mt = 0; mt < 8; mt++)
            #pragma unroll
            for (int nt = 0; nt < 2; nt++)
                #pragma unroll
                for (int v = 0; v < 4; v++) acc[mt][nt][v] = 0.f;

        #pragma unroll 1
        for (int ks = 0; ks < 19; ks++) {
            int kb = ks*8 + 2*tig;
            float2 bf0 = __ldg((const float2*)(g_Wc1I + (nbase + gid)*160 + kb));
            float2 bf1 = __ldg((const float2*)(g_Wc1I + (nbase + 8 + gid)*160 + kb));
            #pragma unroll
            for (int mt = 0; mt < 8; mt++) {
                float2 a01 = *(const float2*)(sm + (mt*16 + gid)*ST1 + kb);
                float2 a23 = *(const float2*)(sm + (mt*16 + 8 + gid)*ST1 + kb);
                mma_tf32(acc[mt][0], a01, a23, bf0);
                mma_tf32(acc[mt][1], a01, a23, bf1);
            }
        }
        __syncthreads();

        #pragma unroll
        for (int mt = 0; mt < 8; mt++)
            #pragma unroll
            for (int nt = 0; nt < 2; nt++)
                #pragma unroll
                for (int v = 0; v < 4; v++) {
                    int row = mt*16 + gid + ((v >> 1) << 3);
                    int col = nbase + nt*8 + 2*tig + (v & 1);
                    float h = acc[mt][nt][v] + __ldg(b1 + col);
                    float s = h / (1.f + __expf(-h));
                    sm[row*ST2 + gpos(col)] = tf32r(s);
                }
        __syncthreads();

        #pragma unroll
        for (int mt = 0; mt < 8; mt++)
            #pragma unroll
            for (int nt = 0; nt < 2; nt++)
                #pragma unroll
                for (int v = 0; v < 4; v++) acc[mt][nt][v] = 0.f;

        #pragma unroll 1
        for (int ks = 0; ks < 16; ks++) {
            int kb = ks*8 + 2*tig;
            float2 bf0 = __ldg((const float2*)(g_W2I + (nbase + gid)*128 + kb));
            float2 bf1 = __ldg((const float2*)(g_W2I + (nbase + 8 + gid)*128 + kb));
            #pragma unroll
            for (int mt = 0; mt < 8; mt++) {
                float2 a01 = *(const float2*)(sm + (mt*16 + gid)*ST2 + kb);
                float2 a23 = *(const float2*)(sm + (mt*16 + 8 + gid)*ST2 + kb);
                mma_tf32(acc[mt][0], a01, a23, bf0);
                mma_tf32(acc[mt][1], a01, a23, bf1);
            }
        }

        #pragma unroll
        for (int mt = 0; mt < 8; mt++)
            #pragma unroll
            for (int nt = 0; nt < 2; nt++)
                #pragma unroll
                for (int h2 = 0; h2 < 2; h2++) {
                    int row = mt*16 + gid + h2*8;
                    int col = nbase + nt*8 + 2*tig;
                    float2 o;
                    o.x = acc[mt][nt][h2*2 + 0] + __ldg(b2 + col);
                    o.y = acc[mt][nt][h2*2 + 1] + __ldg(b2 + col + 1);
                    *(float2*)(out + ((size_t)b*HW_ + hw0 + row)*CC + col) = o;
                }
        __syncthreads();
    }
}

// ---------------------------------------------------------------------------
extern "C" void kernel_launch(void* const* d_in, const int* in_sizes, int n_in,
                              void* d_out, int out_size)
{
    const float* x   = (const float*)d_in[0];
    const float* A1  = (const float*)d_in[1];
    const float* B1  = (const float*)d_in[2];
    const float* A2  = (const float*)d_in[3];
    const float* B2  = (const float*)d_in[4];
    const float* W1  = (const float*)d_in[5];
    const float* b1v = (const float*)d_in[6];
    const float* W2  = (const float*)d_in[7];
    const float* b2v = (const float*)d_in[8];
    const float* cw  = (const float*)d_in[9];
    const float* cf  = (const float*)d_in[10];
    float* out = (float*)d_out;

    cudaFuncSetAttribute(k_fuse, cudaFuncAttributeMaxDynamicSharedMemorySize,
                         SMEM_FL * (int)sizeof(float));
    cudaFuncSetAttribute(k_lora, cudaFuncAttributeMaxDynamicSharedMemorySize,
                         L_SMEM * (int)sizeof(float));

    k_init  <<<1, 256>>>(B1, A2, A1);
    k_init2 <<<8, 256>>>(W1, W2, B2, cw);
    k_lora  <<<NPX/128, 256, L_SMEM * (int)sizeof(float)>>>(x);
    k_num   <<<dim3(HW_/K2CHUNK, 4), 128>>>(cf, B2);
    k_fuse  <<<NBLK, 256, SMEM_FL * (int)sizeof(float)>>>(
                cf, b1v, b2v, B2, out);
}